// round 17
// baseline (speedup 1.0000x reference)
#include <cuda_runtime.h>
#include <cuda_fp16.h>
#include <cstdint>

// Problem dims
#define BATCH 512
#define TSEQ  256
#define CEMB  384
#define HS    64
#define MTOT  (BATCH * TSEQ)

// w pre-converted to half (tiny; prep kernel)
__device__ __half g_wh[CEMB * 192];

__device__ __forceinline__ uint32_t h2u(__half2 h) {
    return *reinterpret_cast<uint32_t*>(&h);
}

// ---------------- raw PTX ----------------
#define LDM_X4(r0, r1, r2, r3, a) \
    asm volatile("ldmatrix.sync.aligned.m8n8.x4.shared.b16 {%0,%1,%2,%3}, [%4];" \
                 : "=r"(r0), "=r"(r1), "=r"(r2), "=r"(r3) : "r"(a))
#define LDM_X4T(r0, r1, r2, r3, a) \
    asm volatile("ldmatrix.sync.aligned.m8n8.x4.trans.shared.b16 {%0,%1,%2,%3}, [%4];" \
                 : "=r"(r0), "=r"(r1), "=r"(r2), "=r"(r3) : "r"(a))
#define CP_ASYNC16(sa, ga) \
    asm volatile("cp.async.cg.shared.global [%0], [%1], 16;" :: "r"(sa), "l"(ga) : "memory")
#define CP_COMMIT() asm volatile("cp.async.commit_group;" ::: "memory")
#define CP_WAIT0()  asm volatile("cp.async.wait_group 0;" ::: "memory")

__device__ __forceinline__ void mma16816(float* c, uint32_t a0, uint32_t a1,
                                         uint32_t a2, uint32_t a3,
                                         uint32_t b0, uint32_t b1) {
    asm volatile(
        "mma.sync.aligned.m16n8k16.row.col.f32.f16.f16.f32 "
        "{%0,%1,%2,%3}, {%4,%5,%6,%7}, {%8,%9}, {%0,%1,%2,%3};"
        : "+f"(c[0]), "+f"(c[1]), "+f"(c[2]), "+f"(c[3])
        : "r"(a0), "r"(a1), "r"(a2), "r"(a3), "r"(b0), "r"(b1));
}

// =============================================================================
// prep: w fp32 -> half (rounding point identical to previous rounds)
// =============================================================================
__global__ void prep_wh(const float* __restrict__ w) {
    int i = blockIdx.x * 256 + threadIdx.x;
    if (i < CEMB * 192) g_wh[i] = __float2half_rn(w[i]);
}

// =============================================================================
// Fused kernel: one CTA per batch (grid 512, 512 threads = 16 warps).
// Phase 1 (proj): 4 m-passes of 64 rows; warp tile 16x48 over 64x192;
//   A: LDG fp32 + convert + STS (double-buffered, ld=40 halves);
//   B: cp.async from g_wh (double-buffered, ld=200 halves);
//   epilogue -> smem Q (scaled) / K / V, row-major ld=72 halves.
// Phase 2 (attn): warp i owns q rows 16i..16i+15; causal kt loop over resident
//   K/V; S/P in registers; deferred normalization; ZERO barriers.
// =============================================================================
#define QKV_LD 72
#define A_LDH  40
#define B_LDH  200
#define OFF_K  (256 * QKV_LD)
#define OFF_V  (2 * 256 * QKV_LD)
#define OFF_A  (3 * 256 * QKV_LD)
#define OFF_B  (OFF_A + 2 * 64 * A_LDH)
#define SMEM_HALVES (OFF_B + 2 * 32 * B_LDH)
#define SMEM_BYTES  (SMEM_HALVES * 2)        // 146432

__global__ __launch_bounds__(512, 1)
void fused_kernel(const float* __restrict__ x, float* __restrict__ out)
{
    extern __shared__ __half sm[];
    __half* Qs = sm;
    __half* Ks = sm + OFF_K;
    __half* Vs = sm + OFF_V;
    __half* As = sm + OFF_A;
    __half* Bs = sm + OFF_B;

    const int tid  = threadIdx.x;
    const int wid  = tid >> 5;
    const int lane = tid & 31;
    const int b    = blockIdx.x;

    const float* xb = x + (size_t)b * TSEQ * CEMB;

    const uint32_t uQs = (uint32_t)__cvta_generic_to_shared(Qs);
    const uint32_t uKs = (uint32_t)__cvta_generic_to_shared(Ks);
    const uint32_t uVs = (uint32_t)__cvta_generic_to_shared(Vs);
    const uint32_t uAs = (uint32_t)__cvta_generic_to_shared(As);
    const uint32_t uBs = (uint32_t)__cvta_generic_to_shared(Bs);

    const int lrow8 = (lane & 7) + ((lane >> 3) & 1) * 8;   // 0..15
    const int lcol8 = (lane >> 4) * 8;                       // 0 or 8

    // ---------------- Phase 1: projection ----------------
    const int wr = (wid & 3) * 16;       // warp row in 64-row pass
    const int wc = (wid >> 2) * 48;      // warp col in 192

    const int a_row = tid >> 3;          // 0..63
    const int a_c4  = (tid & 7) * 4;     // fp32 col 0..28

    // B staging: 768 16B chunks (32 rows x 24 chunks); thread t does t (+512)
    const int bc1_row = tid / 24,        bc1_c8 = tid % 24;
    const int bc2_row = (tid + 512) / 24, bc2_c8 = (tid + 512) % 24;

    const float scale = rsqrtf((float)CEMB);

    for (int mp = 0; mp < 4; mp++) {
        const float* xA = xb + (size_t)(mp * 64 + a_row) * CEMB + a_c4;

        // prologue: chunk 0
        CP_ASYNC16(uBs + (uint32_t)(bc1_row * B_LDH + bc1_c8 * 8) * 2,
                   g_wh + bc1_row * 192 + bc1_c8 * 8);
        if (tid < 256)
            CP_ASYNC16(uBs + (uint32_t)(bc2_row * B_LDH + bc2_c8 * 8) * 2,
                       g_wh + bc2_row * 192 + bc2_c8 * 8);
        CP_COMMIT();
        {
            float4 v = *(const float4*)(xA);
            CP_WAIT0();
            *(uint2*)(As + a_row * A_LDH + a_c4) =
                make_uint2(h2u(__floats2half2_rn(v.x, v.y)), h2u(__floats2half2_rn(v.z, v.w)));
        }
        __syncthreads();

        float acc[6][4];
        #pragma unroll
        for (int nt = 0; nt < 6; nt++)
            #pragma unroll
            for (int e = 0; e < 4; e++) acc[nt][e] = 0.0f;

        float4 a_nxt;
        for (int t = 0; t < 12; t++) {
            if (t < 11) {
                const int k0 = (t + 1) * 32;
                const uint32_t bb = uBs + (uint32_t)(((t + 1) & 1) * 32 * B_LDH) * 2;
                CP_ASYNC16(bb + (uint32_t)(bc1_row * B_LDH + bc1_c8 * 8) * 2,
                           g_wh + (k0 + bc1_row) * 192 + bc1_c8 * 8);
                if (tid < 256)
                    CP_ASYNC16(bb + (uint32_t)(bc2_row * B_LDH + bc2_c8 * 8) * 2,
                               g_wh + (k0 + bc2_row) * 192 + bc2_c8 * 8);
                CP_COMMIT();
                a_nxt = *(const float4*)(xA + k0);
            }

            const uint32_t ab = uAs + (uint32_t)((t & 1) * 64 * A_LDH) * 2;
            const uint32_t bb = uBs + (uint32_t)((t & 1) * 32 * B_LDH) * 2;
            #pragma unroll
            for (int kk = 0; kk < 32; kk += 16) {
                uint32_t a0, a1, a2, a3;
                LDM_X4(a0, a1, a2, a3,
                       ab + (uint32_t)((wr + lrow8) * A_LDH + kk + lcol8) * 2);
                #pragma unroll
                for (int np = 0; np < 3; np++) {
                    uint32_t b0, b1, b2, b3;
                    LDM_X4T(b0, b1, b2, b3,
                            bb + (uint32_t)((kk + lrow8) * B_LDH + wc + np * 16 + lcol8) * 2);
                    mma16816(acc[2 * np],     a0, a1, a2, a3, b0, b1);
                    mma16816(acc[2 * np + 1], a0, a1, a2, a3, b2, b3);
                }
            }

            if (t < 11) {
                __syncthreads();
                *(uint2*)(As + ((t + 1) & 1) * 64 * A_LDH + a_row * A_LDH + a_c4) =
                    make_uint2(h2u(__floats2half2_rn(a_nxt.x, a_nxt.y)),
                               h2u(__floats2half2_rn(a_nxt.z, a_nxt.w)));
                CP_WAIT0();
                __syncthreads();
            }
        }

        // epilogue: write q (scaled) / k / v into resident smem
        const int c0 = 2 * (lane & 3);
        const int lr = mp * 64 + wr + (lane >> 2);
        #pragma unroll
        for (int nt = 0; nt < 6; nt++) {
            const int col   = wc + nt * 8 + c0;
            const int slice = col >> 6;
            const int lcol  = col & 63;
            __half* dst = (slice == 0) ? Qs : ((slice == 1) ? Ks : Vs);
            float f0 = acc[nt][0], f1 = acc[nt][1], f2 = acc[nt][2], f3 = acc[nt][3];
            if (slice == 0) { f0 *= scale; f1 *= scale; f2 *= scale; f3 *= scale; }
            *(__half2*)(dst + lr * QKV_LD + lcol)       = __floats2half2_rn(f0, f1);
            *(__half2*)(dst + (lr + 8) * QKV_LD + lcol) = __floats2half2_rn(f2, f3);
        }
        __syncthreads();
    }

    // ---------------- Phase 2: attention (no barriers) ----------------
    const int qtw  = wid >> 2;          // warp's diagonal key-tile index
    const int wsub = wid & 3;

    uint32_t qf[4][4];
    #pragma unroll
    for (int kc = 0; kc < 4; kc++) {
        LDM_X4(qf[kc][0], qf[kc][1], qf[kc][2], qf[kc][3],
               uQs + (uint32_t)((wid * 16 + lrow8) * QKV_LD + kc * 16 + lcol8) * 2);
    }

    float oacc[8][4];
    #pragma unroll
    for (int n = 0; n < 8; n++)
        #pragma unroll
        for (int e = 0; e < 4; e++) oacc[n][e] = 0.0f;
    float sum0 = 0.0f, sum1 = 0.0f;

    const int r0b = wsub * 16 + (lane >> 2);   // row within 64-block (for mask)
    const int kq  = 2 * (lane & 3);

    for (int kt = 0; kt <= qtw; kt++) {
        const bool diag = (kt == qtw);
        const int ntmax = diag ? (2 * wsub + 2) : 8;
        const int kcmax = diag ? (wsub + 1) : 4;

        float sacc[8][4];
        #pragma unroll
        for (int nt = 0; nt < 8; nt += 2) {
            if (nt < ntmax) {
                #pragma unroll
                for (int e = 0; e < 4; e++) { sacc[nt][e] = 0.0f; sacc[nt + 1][e] = 0.0f; }
                #pragma unroll
                for (int kc = 0; kc < 4; kc++) {
                    uint32_t b0, b1, b2, b3;
                    LDM_X4(b0, b1, b2, b3,
                           uKs + (uint32_t)((kt * 64 + nt * 8 + lrow8) * QKV_LD + kc * 16 + lcol8) * 2);
                    mma16816(sacc[nt],     qf[kc][0], qf[kc][1], qf[kc][2], qf[kc][3], b0, b2);
                    mma16816(sacc[nt + 1], qf[kc][0], qf[kc][1], qf[kc][2], qf[kc][3], b1, b3);
                }
            }
        }

        #pragma unroll
        for (int nt = 0; nt < 8; nt++) {
            if (nt < ntmax) {
                if (diag && nt >= 2 * wsub) {
                    const int k0 = nt * 8 + kq;
                    sacc[nt][0] = (k0     <= r0b)     ? __expf(sacc[nt][0]) : 0.0f;
                    sacc[nt][1] = (k0 + 1 <= r0b)     ? __expf(sacc[nt][1]) : 0.0f;
                    sacc[nt][2] = (k0     <= r0b + 8) ? __expf(sacc[nt][2]) : 0.0f;
                    sacc[nt][3] = (k0 + 1 <= r0b + 8) ? __expf(sacc[nt][3]) : 0.0f;
                } else {
                    sacc[nt][0] = __expf(sacc[nt][0]);
                    sacc[nt][1] = __expf(sacc[nt][1]);
                    sacc[nt][2] = __expf(sacc[nt][2]);
                    sacc[nt][3] = __expf(sacc[nt][3]);
                }
                sum0 += sacc[nt][0] + sacc[nt][1];
                sum1 += sacc[nt][2] + sacc[nt][3];
            }
        }

        #pragma unroll
        for (int kc = 0; kc < 4; kc++) {
            if (kc < kcmax) {
                const uint32_t p0 = h2u(__floats2half2_rn(sacc[2 * kc][0],     sacc[2 * kc][1]));
                const uint32_t p1 = h2u(__floats2half2_rn(sacc[2 * kc][2],     sacc[2 * kc][3]));
                const uint32_t p2 = h2u(__floats2half2_rn(sacc[2 * kc + 1][0], sacc[2 * kc + 1][1]));
                const uint32_t p3 = h2u(__floats2half2_rn(sacc[2 * kc + 1][2], sacc[2 * kc + 1][3]));
                #pragma unroll
                for (int nt = 0; nt < 8; nt += 2) {
                    uint32_t b0, b1, b2, b3;
                    LDM_X4T(b0, b1, b2, b3,
                            uVs + (uint32_t)((kt * 64 + kc * 16 + lrow8) * QKV_LD + nt * 8 + lcol8) * 2);
                    mma16816(oacc[nt],     p0, p1, p2, p3, b0, b1);
                    mma16816(oacc[nt + 1], p0, p1, p2, p3, b2, b3);
                }
            }
        }
    }

    #pragma unroll
    for (int off = 1; off <= 2; off <<= 1) {
        sum0 += __shfl_xor_sync(0xffffffffu, sum0, off);
        sum1 += __shfl_xor_sync(0xffffffffu, sum1, off);
    }
    const float inv0 = 1.0f / sum0;
    const float inv1 = 1.0f / sum1;

    float* o0 = out + (size_t)b * TSEQ * HS + (size_t)(wid * 16 + (lane >> 2)) * HS + kq;
    float* o1 = o0 + 8 * HS;
    #pragma unroll
    for (int nt = 0; nt < 8; nt++) {
        *(float2*)(o0 + nt * 8) = make_float2(oacc[nt][0] * inv0, oacc[nt][1] * inv0);
        *(float2*)(o1 + nt * 8) = make_float2(oacc[nt][2] * inv1, oacc[nt][3] * inv1);
    }
}

// =============================================================================
extern "C" void kernel_launch(void* const* d_in, const int* in_sizes, int n_in,
                              void* d_out, int out_size)
{
    const float* x = (const float*)d_in[0];     // [512,256,384]
    const float* w = (const float*)d_in[1];     // [384,192]
    float* out = (float*)d_out;                 // [512,256,64]

    (void)in_sizes; (void)n_in; (void)out_size;

    static bool attr_set = false;
    if (!attr_set) {
        cudaFuncSetAttribute(fused_kernel, cudaFuncAttributeMaxDynamicSharedMemorySize,
                             SMEM_BYTES);
        attr_set = true;
    }

    prep_wh<<<(CEMB * 192 + 255) / 256, 256>>>(w);
    fused_kernel<<<BATCH, 512, SMEM_BYTES>>>(x, out);
}